// round 3
// baseline (speedup 1.0000x reference)
#include <cuda_runtime.h>
#include <math.h>

// Problem dims (fixed by the dataset)
#define T    2048
#define D    512
#define H    1024
#define H2   2048
#define E    8
#define TOPK 2
#define NSLOT (T*TOPK)   // 4096

// ---------------- scratch (device globals; no allocations allowed) ----------
__device__ int   g_count[E];
__device__ int   g_off[E];
__device__ int   g_list[E*T];        // per-expert token slot lists (slot = t*2+k)
__device__ float g_gate[NSLOT];      // gate value per slot
__device__ float g_probs[E];         // sum of softmax probs per expert (aux loss)
__device__ float g_lsesq;            // sum of lse^2 (aux loss)
__device__ float g_act[(size_t)NSLOT*H2];    // GEMM1 output (pre-GLU), compact rows
__device__ float g_hidden[(size_t)NSLOT*H];  // GLU output, compact rows
__device__ float g_yslot[(size_t)NSLOT*D];   // gate-scaled expert outputs per slot

// ---------------- zero-init (graph replays must reset state) ----------------
__global__ void k_zero() {
    int t = threadIdx.x;
    if (t < E) { g_count[t] = 0; g_probs[t] = 0.f; }
    if (t == 0) g_lsesq = 0.f;
}

// ---------------- router: logits, top-2, gates, scatter, loss partials ------
__global__ __launch_bounds__(256) void k_router(const float* __restrict__ x,
                                                const float* __restrict__ wr) {
    __shared__ float sw[D*E];
    __shared__ float sp[E];
    __shared__ float slse;
    const int tid = threadIdx.x;
    for (int i = tid; i < D*E; i += 256) sw[i] = wr[i];
    if (tid < E) sp[tid] = 0.f;
    if (tid == 0) slse = 0.f;
    __syncthreads();

    const int t = blockIdx.x * 256 + tid;
    float l[E];
#pragma unroll
    for (int j = 0; j < E; j++) l[j] = 0.f;
    const float* xr = x + (size_t)t * D;
    for (int d = 0; d < D; d++) {
        float xv = xr[d];
#pragma unroll
        for (int j = 0; j < E; j++) l[j] = fmaf(xv, sw[d*E + j], l[j]);
    }

    // top-2, matching jax.lax.top_k tie rule (earliest index wins)
    int i1 = 0; float v1 = l[0];
#pragma unroll
    for (int j = 1; j < E; j++) if (l[j] > v1) { v1 = l[j]; i1 = j; }
    int i2 = (i1 == 0) ? 1 : 0; float v2 = l[i2];
#pragma unroll
    for (int j = 0; j < E; j++) if (j != i1 && l[j] > v2) { v2 = l[j]; i2 = j; }

    // softmax over the two top values (v1 >= v2)
    float e2 = expf(v2 - v1);
    float inv = 1.f / (1.f + e2);
    float g1 = inv;
    float g2 = e2 * inv;

    // aux-loss partials: full softmax + logsumexp
    float m = v1;          // v1 is the max logit
    float s = 0.f;
#pragma unroll
    for (int j = 0; j < E; j++) s += expf(l[j] - m);
    float lse = m + logf(s);
    atomicAdd(&slse, lse * lse);
    float invs = 1.f / s;
#pragma unroll
    for (int j = 0; j < E; j++) atomicAdd(&sp[j], expf(l[j] - m) * invs);

    // scatter to per-expert lists
    int p1 = atomicAdd(&g_count[i1], 1);
    g_list[i1*T + p1] = t*2 + 0;
    g_gate[t*2 + 0] = g1;
    int p2 = atomicAdd(&g_count[i2], 1);
    g_list[i2*T + p2] = t*2 + 1;
    g_gate[t*2 + 1] = g2;

    __syncthreads();
    if (tid < E) atomicAdd(&g_probs[tid], sp[tid]);
    if (tid == 0) atomicAdd(&g_lsesq, slse);
}

// ---------------- prefix offsets over E=8 -----------------------------------
__global__ void k_offsets() {
    int o = 0;
    for (int e = 0; e < E; e++) { g_off[e] = o; o += g_count[e]; }
}

// ---------------- GEMM tiling constants -------------------------------------
#define BM 128
#define BN 128
#define BK 16

// GEMM1: act[off+m, n] = sum_d x[tok(m), d] * w_in[e, d, n]   (n in [0, 2H))
__global__ __launch_bounds__(256) void k_gemm1(const float* __restrict__ x,
                                               const float* __restrict__ w_in) {
    const int e   = blockIdx.x >> 4;
    const int rt  = blockIdx.x & 15;
    const int cnt = g_count[e];
    const int m0  = rt * BM;
    if (m0 >= cnt) return;
    const int off = g_off[e];
    const int n0  = blockIdx.y * BN;
    const float* B = w_in + (size_t)e * D * H2;

    __shared__ float s_a[BK][BM];
    __shared__ float s_b[BK][BN];
    __shared__ int   s_tok[BM];

    const int tid = threadIdx.x;
    if (tid < BM) {
        int i = m0 + tid;
        s_tok[tid] = (i < cnt) ? (g_list[e*T + i] >> 1) : (g_list[e*T + m0] >> 1);
    }
    float acc[8][8];
#pragma unroll
    for (int i = 0; i < 8; i++)
#pragma unroll
        for (int j = 0; j < 8; j++) acc[i][j] = 0.f;

    const int tx = tid & 15, ty = tid >> 4;
    __syncthreads();

    for (int d0 = 0; d0 < D; d0 += BK) {
        // load A tile (gathered rows), 512 float4s by 256 threads
        {
            int f = tid;
            int row = f >> 2, kq = f & 3;
            float4 v = *reinterpret_cast<const float4*>(x + (size_t)s_tok[row]*D + d0 + kq*4);
            s_a[kq*4+0][row] = v.x; s_a[kq*4+1][row] = v.y;
            s_a[kq*4+2][row] = v.z; s_a[kq*4+3][row] = v.w;
            f = tid + 256;
            row = f >> 2; kq = f & 3;
            v = *reinterpret_cast<const float4*>(x + (size_t)s_tok[row]*D + d0 + kq*4);
            s_a[kq*4+0][row] = v.x; s_a[kq*4+1][row] = v.y;
            s_a[kq*4+2][row] = v.z; s_a[kq*4+3][row] = v.w;
        }
        // load B tile, fully coalesced
        {
            int f = tid;
            int k = f >> 5, n4 = f & 31;
            *reinterpret_cast<float4*>(&s_b[k][n4*4]) =
                *reinterpret_cast<const float4*>(B + (size_t)(d0+k)*H2 + n0 + n4*4);
            f = tid + 256;
            k = f >> 5; n4 = f & 31;
            *reinterpret_cast<float4*>(&s_b[k][n4*4]) =
                *reinterpret_cast<const float4*>(B + (size_t)(d0+k)*H2 + n0 + n4*4);
        }
        __syncthreads();
#pragma unroll
        for (int k = 0; k < BK; k++) {
            float4 a0 = *reinterpret_cast<float4*>(&s_a[k][ty*8]);
            float4 a1 = *reinterpret_cast<float4*>(&s_a[k][ty*8+4]);
            float4 b0 = *reinterpret_cast<float4*>(&s_b[k][tx*8]);
            float4 b1 = *reinterpret_cast<float4*>(&s_b[k][tx*8+4]);
            float ar[8] = {a0.x,a0.y,a0.z,a0.w,a1.x,a1.y,a1.z,a1.w};
            float br[8] = {b0.x,b0.y,b0.z,b0.w,b1.x,b1.y,b1.z,b1.w};
#pragma unroll
            for (int i = 0; i < 8; i++)
#pragma unroll
                for (int j = 0; j < 8; j++) acc[i][j] = fmaf(ar[i], br[j], acc[i][j]);
        }
        __syncthreads();
    }
#pragma unroll
    for (int i = 0; i < 8; i++) {
        int m = m0 + ty*8 + i;
        if (m < cnt) {
            float* dst = g_act + (size_t)(off + m)*H2 + n0 + tx*8;
            *reinterpret_cast<float4*>(dst)   = make_float4(acc[i][0],acc[i][1],acc[i][2],acc[i][3]);
            *reinterpret_cast<float4*>(dst+4) = make_float4(acc[i][4],acc[i][5],acc[i][6],acc[i][7]);
        }
    }
}

// ---------------- GLU: hidden = silu(act[:, :H]) * act[:, H:] ---------------
__global__ void k_glu() {
    int idx = blockIdx.x * 256 + threadIdx.x;   // over NSLOT*H/4
    int r  = idx >> 8;                          // H/4 = 256 float4 per row
    int j4 = idx & 255;
    const float4 a = *reinterpret_cast<const float4*>(g_act + (size_t)r*H2 + j4*4);
    const float4 g = *reinterpret_cast<const float4*>(g_act + (size_t)r*H2 + H + j4*4);
    float4 h;
    h.x = (a.x / (1.f + expf(-a.x))) * g.x;
    h.y = (a.y / (1.f + expf(-a.y))) * g.y;
    h.z = (a.z / (1.f + expf(-a.z))) * g.z;
    h.w = (a.w / (1.f + expf(-a.w))) * g.w;
    *reinterpret_cast<float4*>(g_hidden + (size_t)r*H + j4*4) = h;
}

// GEMM2: yslot[slot, n] = gate[slot] * sum_h hidden[off+m, h] * w_out[e, h, n]
__global__ __launch_bounds__(256) void k_gemm2(const float* __restrict__ w_out) {
    const int e   = blockIdx.x >> 4;
    const int rt  = blockIdx.x & 15;
    const int cnt = g_count[e];
    const int m0  = rt * BM;
    if (m0 >= cnt) return;
    const int off = g_off[e];
    const int n0  = blockIdx.y * BN;
    const float* B = w_out + (size_t)e * H * D;

    __shared__ float s_a[BK][BM];
    __shared__ float s_b[BK][BN];

    const int tid = threadIdx.x;
    float acc[8][8];
#pragma unroll
    for (int i = 0; i < 8; i++)
#pragma unroll
        for (int j = 0; j < 8; j++) acc[i][j] = 0.f;

    const int tx = tid & 15, ty = tid >> 4;
    const int cmax = cnt - 1;
    __syncthreads();

    for (int d0 = 0; d0 < H; d0 += BK) {
        {
            int f = tid;
            int row = f >> 2, kq = f & 3;
            int r = off + min(m0 + row, cmax);
            float4 v = *reinterpret_cast<const float4*>(g_hidden + (size_t)r*H + d0 + kq*4);
            s_a[kq*4+0][row] = v.x; s_a[kq*4+1][row] = v.y;
            s_a[kq*4+2][row] = v.z; s_a[kq*4+3][row] = v.w;
            f = tid + 256;
            row = f >> 2; kq = f & 3;
            r = off + min(m0 + row, cmax);
            v = *reinterpret_cast<const float4*>(g_hidden + (size_t)r*H + d0 + kq*4);
            s_a[kq*4+0][row] = v.x; s_a[kq*4+1][row] = v.y;
            s_a[kq*4+2][row] = v.z; s_a[kq*4+3][row] = v.w;
        }
        {
            int f = tid;
            int k = f >> 5, n4 = f & 31;
            *reinterpret_cast<float4*>(&s_b[k][n4*4]) =
                *reinterpret_cast<const float4*>(B + (size_t)(d0+k)*D + n0 + n4*4);
            f = tid + 256;
            k = f >> 5; n4 = f & 31;
            *reinterpret_cast<float4*>(&s_b[k][n4*4]) =
                *reinterpret_cast<const float4*>(B + (size_t)(d0+k)*D + n0 + n4*4);
        }
        __syncthreads();
#pragma unroll
        for (int k = 0; k < BK; k++) {
            float4 a0 = *reinterpret_cast<float4*>(&s_a[k][ty*8]);
            float4 a1 = *reinterpret_cast<float4*>(&s_a[k][ty*8+4]);
            float4 b0 = *reinterpret_cast<float4*>(&s_b[k][tx*8]);
            float4 b1 = *reinterpret_cast<float4*>(&s_b[k][tx*8+4]);
            float ar[8] = {a0.x,a0.y,a0.z,a0.w,a1.x,a1.y,a1.z,a1.w};
            float br[8] = {b0.x,b0.y,b0.z,b0.w,b1.x,b1.y,b1.z,b1.w};
#pragma unroll
            for (int i = 0; i < 8; i++)
#pragma unroll
                for (int j = 0; j < 8; j++) acc[i][j] = fmaf(ar[i], br[j], acc[i][j]);
        }
        __syncthreads();
    }
#pragma unroll
    for (int i = 0; i < 8; i++) {
        int m = m0 + ty*8 + i;
        if (m < cnt) {
            int slot = g_list[e*T + m];
            float gv = g_gate[slot];
            float* dst = g_yslot + (size_t)slot*D + n0 + tx*8;
            *reinterpret_cast<float4*>(dst) =
                make_float4(gv*acc[i][0], gv*acc[i][1], gv*acc[i][2], gv*acc[i][3]);
            *reinterpret_cast<float4*>(dst+4) =
                make_float4(gv*acc[i][4], gv*acc[i][5], gv*acc[i][6], gv*acc[i][7]);
        }
    }
}

// ---------------- combine: y[t] = yslot[2t] + yslot[2t+1] + bias ------------
__global__ void k_combine(float* __restrict__ out, const float* __restrict__ bias) {
    int idx = blockIdx.x * 256 + threadIdx.x;   // over T*D/4
    int t  = idx >> 7;                           // D/4 = 128 float4 per token
    int n  = (idx & 127) * 4;
    float4 a = *reinterpret_cast<const float4*>(g_yslot + (size_t)(2*t)*D + n);
    float4 b = *reinterpret_cast<const float4*>(g_yslot + (size_t)(2*t+1)*D + n);
    float4 bb = *reinterpret_cast<const float4*>(bias + n);
    float4 y = make_float4(a.x+b.x+bb.x, a.y+b.y+bb.y, a.z+b.z+bb.z, a.w+b.w+bb.w);
    *reinterpret_cast<float4*>(out + (size_t)t*D + n) = y;
}

// ---------------- aux loss finalize -----------------------------------------
__global__ void k_loss(float* out, int out_size) {
    if (out_size <= T*D) return;
    float ps = 0.f;
    for (int e = 0; e < E; e++) ps += g_probs[e];
    float sl = 0.f;
    for (int e = 0; e < E; e++)
        sl += (g_probs[e] / ps) * ((float)g_count[e] / (float)NSLOT);
    float switchloss = (float)E * sl;
    float zloss = g_lsesq / (float)T;
    out[T*D] = switchloss + 0.1f * zloss;
}

// ---------------- launch -----------------------------------------------------
extern "C" void kernel_launch(void* const* d_in, const int* in_sizes, int n_in,
                              void* d_out, int out_size) {
    const float* x     = (const float*)d_in[0];
    const float* wr    = (const float*)d_in[1];
    const float* w_in  = (const float*)d_in[2];
    const float* w_out = (const float*)d_in[3];
    const float* bias  = (const float*)d_in[4];
    float* out = (float*)d_out;

    k_zero<<<1, 32>>>();
    k_router<<<T/256, 256>>>(x, wr);
    k_offsets<<<1, 1>>>();
    k_gemm1<<<dim3(E*16, H2/BN), 256>>>(x, w_in);
    k_glu<<<(NSLOT*H/4)/256, 256>>>();
    k_gemm2<<<dim3(E*16, D/BN), 256>>>(w_out);
    k_combine<<<(T*D/4)/256, 256>>>(out, bias);
    k_loss<<<1, 1>>>(out, out_size);
}

// round 5
// speedup vs baseline: 1.6057x; 1.6057x over previous
#include <cuda_runtime.h>
#include <math.h>
#include <stdint.h>

// Problem dims (fixed by the dataset)
#define T    2048
#define D    512
#define H    1024
#define H2   2048
#define E    8
#define NSLOT (T*2)   // 4096

// ---------------- scratch (device globals; no allocations allowed) ----------
__device__ int   g_count[E];
__device__ int   g_off[E];
__device__ int   g_list[E*T];        // per-expert token slot lists (slot = t*2+k)
__device__ float g_gate[NSLOT];      // gate value per slot
__device__ float g_probs[E];         // sum of softmax probs per expert (aux loss)
__device__ float g_lsesq;            // sum of lse^2 (aux loss)
__device__ float g_hidden[(size_t)NSLOT*H];  // GLU output, compact rows
__device__ float g_yslot[(size_t)NSLOT*D];   // gate-scaled expert outputs per slot

// ======================= helpers =============================================
__device__ __forceinline__ uint32_t smem_u32(const void* p) {
    uint32_t a;
    asm("{ .reg .u64 t; cvta.to.shared.u64 t, %1; cvt.u32.u64 %0, t; }" : "=r"(a) : "l"(p));
    return a;
}
#define CP16(dst, src) \
    asm volatile("cp.async.cg.shared.global [%0], [%1], 16;" :: "r"(dst), "l"(src) : "memory")
#define CP_COMMIT() asm volatile("cp.async.commit_group;" ::: "memory")
#define CP_WAIT1()  asm volatile("cp.async.wait_group 1;" ::: "memory")
#define CP_WAIT0()  asm volatile("cp.async.wait_group 0;" ::: "memory")

// 3xTF32 split: x = hi + lo (both tf32-representable, bit patterns in u32)
__device__ __forceinline__ void split_tf32(float x, uint32_t& hi, uint32_t& lo) {
    asm("cvt.rna.tf32.f32 %0, %1;" : "=r"(hi) : "f"(x));
    float lf = x - __uint_as_float(hi);
    asm("cvt.rna.tf32.f32 %0, %1;" : "=r"(lo) : "f"(lf));
}

#define MMA_TF32(d, a, b0, b1) \
    asm volatile("mma.sync.aligned.m16n8k8.row.col.f32.tf32.tf32.f32 " \
        "{%0,%1,%2,%3},{%4,%5,%6,%7},{%8,%9},{%0,%1,%2,%3};" \
        : "+f"((d)[0]), "+f"((d)[1]), "+f"((d)[2]), "+f"((d)[3]) \
        : "r"((a)[0]), "r"((a)[1]), "r"((a)[2]), "r"((a)[3]), "r"(b0), "r"(b1))

// ---------------- zero-init (graph replays must reset state) ----------------
__global__ void k_zero() {
    int t = threadIdx.x;
    if (t < E) { g_count[t] = 0; g_probs[t] = 0.f; }
    if (t == 0) g_lsesq = 0.f;
}

// ---------------- router: logits, top-2, gates, scatter, loss partials ------
__global__ __launch_bounds__(256) void k_router(const float* __restrict__ x,
                                                const float* __restrict__ wr) {
    __shared__ float sw[D*E];
    __shared__ float sp[E];
    __shared__ float slse;
    const int tid = threadIdx.x;
    for (int i = tid; i < D*E; i += 256) sw[i] = wr[i];
    if (tid < E) sp[tid] = 0.f;
    if (tid == 0) slse = 0.f;
    __syncthreads();

    const int t = blockIdx.x * 256 + tid;
    float l[E];
#pragma unroll
    for (int j = 0; j < E; j++) l[j] = 0.f;
    const float4* xr4 = reinterpret_cast<const float4*>(x + (size_t)t * D);
    for (int d4 = 0; d4 < D/4; d4++) {
        float4 v = xr4[d4];
        int d = d4 * 4;
#pragma unroll
        for (int j = 0; j < E; j++) {
            l[j] = fmaf(v.x, sw[(d+0)*E + j], l[j]);
            l[j] = fmaf(v.y, sw[(d+1)*E + j], l[j]);
            l[j] = fmaf(v.z, sw[(d+2)*E + j], l[j]);
            l[j] = fmaf(v.w, sw[(d+3)*E + j], l[j]);
        }
    }

    // top-2, matching jax.lax.top_k tie rule (earliest index wins)
    int i1 = 0; float v1 = l[0];
#pragma unroll
    for (int j = 1; j < E; j++) if (l[j] > v1) { v1 = l[j]; i1 = j; }
    int i2 = (i1 == 0) ? 1 : 0; float v2 = l[i2];
#pragma unroll
    for (int j = 0; j < E; j++) if (j != i1 && l[j] > v2) { v2 = l[j]; i2 = j; }

    float e2 = expf(v2 - v1);
    float inv = 1.f / (1.f + e2);
    float g1 = inv;
    float g2 = e2 * inv;

    float m = v1;
    float s = 0.f;
#pragma unroll
    for (int j = 0; j < E; j++) s += expf(l[j] - m);
    float lse = m + logf(s);
    atomicAdd(&slse, lse * lse);
    float invs = 1.f / s;
#pragma unroll
    for (int j = 0; j < E; j++) atomicAdd(&sp[j], expf(l[j] - m) * invs);

    int p1 = atomicAdd(&g_count[i1], 1);
    g_list[i1*T + p1] = t*2 + 0;
    g_gate[t*2 + 0] = g1;
    int p2 = atomicAdd(&g_count[i2], 1);
    g_list[i2*T + p2] = t*2 + 1;
    g_gate[t*2 + 1] = g2;

    __syncthreads();
    if (tid < E) atomicAdd(&g_probs[tid], sp[tid]);
    if (tid == 0) atomicAdd(&g_lsesq, slse);
}

// ---------------- prefix offsets over E=8 -----------------------------------
__global__ void k_offsets() {
    int o = 0;
    for (int e = 0; e < E; e++) { g_off[e] = o; o += g_count[e]; }
}

// ============================================================================
// GEMM1 (mma.sync tf32, 3x split) fused with GLU.
// CTA: 128 gathered tokens x 128 h-cols + matching 128 gate-cols. K=512.
// 8 warps as 4(m) x 2(n): warp tile 32 x 64 per half.
// SMEM (per stage): A raw fp32 [128][20] (pad 4), B raw fp32 [16][264] (pad 8,
// cols 0..127 = h half, 128..255 = gate half).
// ============================================================================
#define AS 20
#define BS1 264
#define G1_A_STG (128*AS*4)              // 10240
#define G1_B_STG (16*BS1*4)              // 16896
#define G1_SMEM  (2*G1_A_STG + 2*G1_B_STG)

__global__ __launch_bounds__(256, 1) void k_gemm1(const float* __restrict__ x,
                                                  const float* __restrict__ w_in) {
    const int e   = blockIdx.x >> 4;
    const int rt  = blockIdx.x & 15;
    const int cnt = g_count[e];
    const int m0  = rt * 128;
    if (m0 >= cnt) return;
    const int off = g_off[e];
    const int n0  = blockIdx.y * 128;

    extern __shared__ char smem[];
    __shared__ int s_tok[128];
    float* sA[2] = { (float*)smem, (float*)(smem + G1_A_STG) };
    float* sB[2] = { (float*)(smem + 2*G1_A_STG), (float*)(smem + 2*G1_A_STG + G1_B_STG) };

    const int tid  = threadIdx.x;
    const int wid  = tid >> 5;
    const int lane = tid & 31;
    const int wm   = wid & 3;        // 0..3 -> m offset wm*32
    const int wn   = wid >> 2;       // 0..1 -> n offset wn*64

    if (tid < 128) {
        int i = m0 + tid;
        s_tok[tid] = g_list[e*T + min(i, cnt-1)] >> 1;
    }
    __syncthreads();

    const float* W = w_in + (size_t)e * D * H2;

    // stage loader
    auto load_stage = [&](int it, int buf) {
        const int d0 = it * 16;
        // A: 128 rows x 16 floats = 512 x 16B
        float* a = sA[buf];
#pragma unroll
        for (int r = 0; r < 2; r++) {
            int i = tid + r*256;
            int row = i >> 2, q = i & 3;
            uint32_t dst = smem_u32(a + row*AS + q*4);
            CP16(dst, x + (size_t)s_tok[row]*D + d0 + q*4);
        }
        // B: 16 rows x 256 floats = 1024 x 16B
        float* b = sB[buf];
#pragma unroll
        for (int r = 0; r < 4; r++) {
            int i = tid + r*256;
            int k = i >> 6, c = i & 63;
            int n = c * 4;
            int gc = (n < 128) ? (n0 + n) : (H + n0 + (n - 128));
            uint32_t dst = smem_u32(b + k*BS1 + n);
            CP16(dst, W + (size_t)(d0 + k)*H2 + gc);
        }
        CP_COMMIT();
    };

    float acc[2][8][2][4];
#pragma unroll
    for (int h2 = 0; h2 < 2; h2++)
#pragma unroll
        for (int nf = 0; nf < 8; nf++)
#pragma unroll
            for (int mf = 0; mf < 2; mf++)
#pragma unroll
                for (int r = 0; r < 4; r++) acc[h2][nf][mf][r] = 0.f;

    const int NIT = D / 16;   // 32
    load_stage(0, 0);
    load_stage(1, 1);

    const int rA = wm*32 + (lane >> 2);
    const int kA = lane & 3;
    const int nB = wn*64 + (lane >> 2);

    for (int it = 0; it < NIT; it++) {
        if (it + 1 < NIT) CP_WAIT1(); else CP_WAIT0();
        __syncthreads();
        const int buf = it & 1;
        const float* a = sA[buf];
        const float* b = sB[buf];
#pragma unroll
        for (int ks = 0; ks < 2; ks++) {
            const int k0 = ks * 8;
            uint32_t ahi[2][4], alo[2][4];
#pragma unroll
            for (int mf = 0; mf < 2; mf++) {
                int rr = rA + mf*16;
                split_tf32(a[(rr  )*AS + k0 + kA    ], ahi[mf][0], alo[mf][0]);
                split_tf32(a[(rr+8)*AS + k0 + kA    ], ahi[mf][1], alo[mf][1]);
                split_tf32(a[(rr  )*AS + k0 + kA + 4], ahi[mf][2], alo[mf][2]);
                split_tf32(a[(rr+8)*AS + k0 + kA + 4], ahi[mf][3], alo[mf][3]);
            }
#pragma unroll
            for (int h2 = 0; h2 < 2; h2++) {
#pragma unroll
                for (int nf = 0; nf < 8; nf++) {
                    int n = h2*128 + nB + nf*8;
                    uint32_t bh0, bl0, bh1, bl1;
                    split_tf32(b[(k0 + kA    )*BS1 + n], bh0, bl0);
                    split_tf32(b[(k0 + kA + 4)*BS1 + n], bh1, bl1);
                    MMA_TF32(acc[h2][nf][0], ahi[0], bh0, bh1);
                    MMA_TF32(acc[h2][nf][1], ahi[1], bh0, bh1);
                    MMA_TF32(acc[h2][nf][0], ahi[0], bl0, bl1);
                    MMA_TF32(acc[h2][nf][1], ahi[1], bl0, bl1);
                    MMA_TF32(acc[h2][nf][0], alo[0], bh0, bh1);
                    MMA_TF32(acc[h2][nf][1], alo[1], bh0, bh1);
                }
            }
        }
        __syncthreads();
        if (it + 2 < NIT) load_stage(it + 2, buf);
    }

    // Epilogue: h = silu(a)*g -> g_hidden  (c0,c1 at row; c2,c3 at row+8)
#pragma unroll
    for (int mf = 0; mf < 2; mf++) {
#pragma unroll
        for (int rr = 0; rr < 2; rr++) {
            int m = m0 + wm*32 + mf*16 + (lane >> 2) + rr*8;
            if (m < cnt) {
                float* drow = g_hidden + (size_t)(off + m)*H + n0;
#pragma unroll
                for (int nf = 0; nf < 8; nf++) {
                    int col = wn*64 + nf*8 + 2*(lane & 3);
                    float a0 = acc[0][nf][mf][rr*2+0], g0v = acc[1][nf][mf][rr*2+0];
                    float a1 = acc[0][nf][mf][rr*2+1], g1v = acc[1][nf][mf][rr*2+1];
                    float2 o;
                    o.x = (a0 / (1.f + expf(-a0))) * g0v;
                    o.y = (a1 / (1.f + expf(-a1))) * g1v;
                    *reinterpret_cast<float2*>(drow + col) = o;
                }
            }
        }
    }
}

// ============================================================================
// GEMM2 (mma.sync tf32, 3x split): yslot = gate * (hidden @ w_out[e])
// CTA: 128 slots x 128 out-cols. K=1024.
// ============================================================================
#define BS2 136
#define G2_A_STG (128*AS*4)              // 10240
#define G2_B_STG (16*BS2*4)              // 8704
#define G2_SMEM  (2*G2_A_STG + 2*G2_B_STG)

__global__ __launch_bounds__(256, 1) void k_gemm2(const float* __restrict__ w_out) {
    const int e   = blockIdx.x >> 4;
    const int rt  = blockIdx.x & 15;
    const int cnt = g_count[e];
    const int m0  = rt * 128;
    if (m0 >= cnt) return;
    const int off = g_off[e];
    const int n0  = blockIdx.y * 128;
    const int cmax = cnt - 1;

    extern __shared__ char smem[];
    float* sA[2] = { (float*)smem, (float*)(smem + G2_A_STG) };
    float* sB[2] = { (float*)(smem + 2*G2_A_STG), (float*)(smem + 2*G2_A_STG + G2_B_STG) };

    const int tid  = threadIdx.x;
    const int wid  = tid >> 5;
    const int lane = tid & 31;
    const int wm   = wid & 3;
    const int wn   = wid >> 2;

    const float* W = w_out + (size_t)e * H * D;

    auto load_stage = [&](int it, int buf) {
        const int h0 = it * 16;
        float* a = sA[buf];
#pragma unroll
        for (int r = 0; r < 2; r++) {
            int i = tid + r*256;
            int row = i >> 2, q = i & 3;
            int gr = off + min(m0 + row, cmax);
            uint32_t dst = smem_u32(a + row*AS + q*4);
            CP16(dst, g_hidden + (size_t)gr*H + h0 + q*4);
        }
        float* b = sB[buf];
        {
            int i = tid;                 // 16 rows x 32 chunks = 512
            int k = i >> 5, c = i & 31;
            uint32_t dst = smem_u32(b + k*BS2 + c*4);
            CP16(dst, W + (size_t)(h0 + k)*D + n0 + c*4);
            i = tid + 256;
            k = i >> 5; c = i & 31;
            dst = smem_u32(b + k*BS2 + c*4);
            CP16(dst, W + (size_t)(h0 + k)*D + n0 + c*4);
        }
        CP_COMMIT();
    };

    float acc[8][2][4];
#pragma unroll
    for (int nf = 0; nf < 8; nf++)
#pragma unroll
        for (int mf = 0; mf < 2; mf++)
#pragma unroll
            for (int r = 0; r < 4; r++) acc[nf][mf][r] = 0.f;

    const int NIT = H / 16;   // 64
    load_stage(0, 0);
    load_stage(1, 1);

    const int rA = wm*32 + (lane >> 2);
    const int kA = lane & 3;
    const int nB = wn*64 + (lane >> 2);

    for (int it = 0; it < NIT; it++) {
        if (it + 1 < NIT) CP_WAIT1(); else CP_WAIT0();
        __syncthreads();
        const int buf = it & 1;
        const float* a = sA[buf];
        const float* b = sB[buf];
#pragma unroll
        for (int ks = 0; ks < 2; ks++) {
            const int k0 = ks * 8;
            uint32_t ahi[2][4], alo[2][4];
#pragma unroll
            for (int mf = 0; mf < 2; mf++) {
                int rr = rA + mf*16;
                split_tf32(a[(rr  )*AS + k0 + kA    ], ahi[mf][0], alo[mf][0]);
                split_tf32(a[(rr+8)*AS + k0 + kA    ], ahi[mf][1], alo[mf][1]);
                split_tf32(a[(rr  )*AS + k0 + kA + 4], ahi[mf][2], alo[mf][2]);
                split_tf32(a[(rr+8)*AS + k0 + kA + 4], ahi[mf][3], alo[mf][3]);
            }
#pragma unroll
            for (int nf = 0; nf < 8; nf++) {
                int n = nB + nf*8;
                uint32_t bh0, bl0, bh1, bl1;
                split_tf32(b[(k0 + kA    )*BS2 + n], bh0, bl0);
                split_tf32(b[(k0 + kA + 4)*BS2 + n], bh1, bl1);
                MMA_TF32(acc[nf][0], ahi[0], bh0, bh1);
                MMA_TF32(acc[nf][1], ahi[1], bh0, bh1);
                MMA_TF32(acc[nf][0], ahi[0], bl0, bl1);
                MMA_TF32(acc[nf][1], ahi[1], bl0, bl1);
                MMA_TF32(acc[nf][0], alo[0], bh0, bh1);
                MMA_TF32(acc[nf][1], alo[1], bh0, bh1);
            }
        }
        __syncthreads();
        if (it + 2 < NIT) load_stage(it + 2, buf);
    }

    // Epilogue: scale by gate, scatter to yslot
#pragma unroll
    for (int mf = 0; mf < 2; mf++) {
#pragma unroll
        for (int rr = 0; rr < 2; rr++) {
            int m = m0 + wm*32 + mf*16 + (lane >> 2) + rr*8;
            if (m < cnt) {
                int slot = g_list[e*T + m];
                float gv = g_gate[slot];
                float* drow = g_yslot + (size_t)slot*D + n0;
#pragma unroll
                for (int nf = 0; nf < 8; nf++) {
                    int col = wn*64 + nf*8 + 2*(lane & 3);
                    float2 o;
                    o.x = gv * acc[nf][mf][rr*2+0];
                    o.y = gv * acc[nf][mf][rr*2+1];
                    *reinterpret_cast<float2*>(drow + col) = o;
                }
            }
        }
    }
}

// ---------------- combine: y[t] = yslot[2t] + yslot[2t+1] + bias ------------
__global__ void k_combine(float* __restrict__ out, const float* __restrict__ bias) {
    int idx = blockIdx.x * 256 + threadIdx.x;   // over T*D/4
    int t = idx >> 7;
    int n = (idx & 127) * 4;
    float4 a = *reinterpret_cast<const float4*>(g_yslot + (size_t)(2*t)*D + n);
    float4 b = *reinterpret_cast<const float4*>(g_yslot + (size_t)(2*t+1)*D + n);
    float4 bb = *reinterpret_cast<const float4*>(bias + n);
    float4 y = make_float4(a.x+b.x+bb.x, a.y+b.y+bb.y, a.z+b.z+bb.z, a.w+b.w+bb.w);
    *reinterpret_cast<float4*>(out + (size_t)t*D + n) = y;
}

// ---------------- aux loss finalize -----------------------------------------
__global__ void k_loss(float* out, int out_size) {
    if (out_size <= T*D) return;
    float ps = 0.f;
    for (int e = 0; e < E; e++) ps += g_probs[e];
    float sl = 0.f;
    for (int e = 0; e < E; e++)
        sl += (g_probs[e] / ps) * ((float)g_count[e] / (float)NSLOT);
    float switchloss = (float)E * sl;
    float zloss = g_lsesq / (float)T;
    out[T*D] = switchloss + 0.1f * zloss;
}

// ---------------- launch -----------------------------------------------------
extern "C" void kernel_launch(void* const* d_in, const int* in_sizes, int n_in,
                              void* d_out, int out_size) {
    const float* x     = (const float*)d_in[0];
    const float* wr    = (const float*)d_in[1];
    const float* w_in  = (const float*)d_in[2];
    const float* w_out = (const float*)d_in[3];
    const float* bias  = (const float*)d_in[4];
    float* out = (float*)d_out;

    cudaFuncSetAttribute(k_gemm1, cudaFuncAttributeMaxDynamicSharedMemorySize, G1_SMEM);
    cudaFuncSetAttribute(k_gemm2, cudaFuncAttributeMaxDynamicSharedMemorySize, G2_SMEM);

    k_zero<<<1, 32>>>();
    k_router<<<T/256, 256>>>(x, wr);
    k_offsets<<<1, 1>>>();
    k_gemm1<<<dim3(E*16, H/128), 256, G1_SMEM>>>(x, w_in);
    k_gemm2<<<dim3(E*16, D/128), 256, G2_SMEM>>>(w_out);
    k_combine<<<(T*D/4)/256, 256>>>(out, bias);
    k_loss<<<1, 1>>>(out, out_size);
}